// round 4
// baseline (speedup 1.0000x reference)
#include <cuda_runtime.h>

#define NH 128
#define NI 64
#define NO 10
#define NB 128
#define S_MAX 2048

// 128 MiB scratch for the precomputed input projection xW[S,B,H].
__device__ __align__(16) float g_xw[(size_t)S_MAX * NB * NH];

// ---- packed f32x2 helpers (sm_100+ PTX) ----
__device__ __forceinline__ unsigned long long ffma2(unsigned long long a,
                                                    unsigned long long b,
                                                    unsigned long long c) {
    unsigned long long d;
    asm("fma.rn.f32x2 %0, %1, %2, %3;" : "=l"(d) : "l"(a), "l"(b), "l"(c));
    return d;
}
__device__ __forceinline__ unsigned long long packf2(float lo, float hi) {
    unsigned long long r;
    asm("mov.b64 %0, {%1, %2};" : "=l"(r) : "f"(lo), "f"(hi));
    return r;
}
__device__ __forceinline__ float2 unpackf2(unsigned long long v) {
    float2 f;
    asm("mov.b64 {%0, %1}, %2;" : "=f"(f.x), "=f"(f.y) : "l"(v));
    return f;
}

// ============================================================
// K1: xW[s,b,j] = x[s,b,:] @ Wxh[:,j] + bh[j]
// grid = seq, block = 512 (p = tid>>7 in 0..3 splits batch rows 4-way)
// ============================================================
__global__ void __launch_bounds__(512, 1) xw_gemm_kernel(
    const float* __restrict__ x, const float* __restrict__ Wxh,
    const float* __restrict__ bh, int seq)
{
    const int s = blockIdx.x;
    __shared__ __align__(16) float xs[NB * NI];  // 32 KB: x[s,:,:]

    const float4* xin = reinterpret_cast<const float4*>(x + (long long)s * NB * NI);
    float4* xs4 = reinterpret_cast<float4*>(xs);
#pragma unroll
    for (int i = threadIdx.x; i < NB * NI / 4; i += 512) xs4[i] = xin[i];

    const int j = threadIdx.x & 127;
    const int p = threadIdx.x >> 7;   // 0..3

    unsigned long long w2[NI / 2];
#pragma unroll
    for (int m = 0; m < NI / 2; m++)
        w2[m] = packf2(Wxh[(2 * m) * NH + j], Wxh[(2 * m + 1) * NH + j]);
    const unsigned long long bias2 = packf2(bh[j], 0.0f);
    __syncthreads();

    float* outrow = g_xw + (long long)s * NB * NH;
#pragma unroll
    for (int b = p; b < NB; b += 4) {
        const ulonglong2* xr = reinterpret_cast<const ulonglong2*>(xs + b * NI);
        unsigned long long a0 = bias2, a1 = 0ull, a2 = 0ull, a3 = 0ull;
#pragma unroll
        for (int m = 0; m < NI / 4; m++) {  // 16 LDS.128, 32 FFMA2
            ulonglong2 xv = xr[m];
            if (m & 1) { a2 = ffma2(xv.x, w2[2 * m], a2); a3 = ffma2(xv.y, w2[2 * m + 1], a3); }
            else       { a0 = ffma2(xv.x, w2[2 * m], a0); a1 = ffma2(xv.y, w2[2 * m + 1], a1); }
        }
        float2 f0 = unpackf2(a0), f1 = unpackf2(a1), f2 = unpackf2(a2), f3 = unpackf2(a3);
        outrow[b * NH + j] =
            ((f0.x + f0.y) + (f1.x + f1.y)) + ((f2.x + f2.y) + (f3.x + f3.y));
    }
}

// ============================================================
// K2: sequential scan, TWO independent batch chains per CTA.
// grid = NB/2, block = 256. cid = tid>>7 selects the chain
// (warps 0-3 -> chain 2*bid, warps 4-7 -> chain 2*bid+1), j = tid&127
// owns hidden column j of its chain. 2 warps/SMSP with independent
// ld->fma streams hide each other's LDS latency. One barrier per step.
// ============================================================
__global__ void __launch_bounds__(256, 1) rnn_scan_kernel(
    const float* __restrict__ Whh, const float* __restrict__ Why,
    const float* __restrict__ by, float* __restrict__ out, int seq)
{
    const int cid = threadIdx.x >> 7;       // chain slot 0/1
    const int j   = threadIdx.x & 127;      // hidden column
    const int b   = 2 * blockIdx.x + cid;   // batch row

    // Whh column j, packed to match ulonglong2 (LDS.128) h pairs
    unsigned long long w2[NH / 2];
#pragma unroll
    for (int k = 0; k < NH / 2; k++)
        w2[k] = packf2(Whh[(2 * k) * NH + j], Whh[(2 * k + 1) * NH + j]);

    __shared__ __align__(16) float hsh[2][2][NH];   // [chain][buf][col]
    hsh[cid][0][j] = 0.0f;

    // xw prefetch ring, depth 4 (covers DRAM latency)
    const float* xwb = g_xw + (long long)b * NH + j;
    float xq[4];
#pragma unroll
    for (int q = 0; q < 4; q++)
        xq[q] = (q < seq) ? xwb[(long long)q * NB * NH] : 0.0f;

    float* h_out = out + NB * NO;
    __syncthreads();

    int hb = 0;
#pragma unroll 4
    for (int t = 0; t < seq; t++) {
        unsigned long long a0 = packf2(xq[t & 3], 0.0f);
        unsigned long long a1 = 0ull, a2 = 0ull, a3 = 0ull;
        if (t + 4 < seq)
            xq[t & 3] = xwb[(long long)(t + 4) * NB * NH];

        const ulonglong2* h2 = reinterpret_cast<const ulonglong2*>(hsh[cid][hb]);
#pragma unroll
        for (int m = 0; m < NH / 4; m++) {  // 32 LDS.128 (broadcast), 64 FFMA2
            ulonglong2 hv = h2[m];
            if (m & 1) { a2 = ffma2(hv.x, w2[2 * m], a2); a3 = ffma2(hv.y, w2[2 * m + 1], a3); }
            else       { a0 = ffma2(hv.x, w2[2 * m], a0); a1 = ffma2(hv.y, w2[2 * m + 1], a1); }
        }
        float2 f0 = unpackf2(a0), f1 = unpackf2(a1), f2 = unpackf2(a2), f3 = unpackf2(a3);
        float v = ((f0.x + f0.y) + (f1.x + f1.y)) + ((f2.x + f2.y) + (f3.x + f3.y));

        // accurate tanh via exp2/rcp (MUFU); approx-tanh's 1e-3 abs error
        // would random-walk past tolerance over 2048 steps
        float a = fabsf(v);
        float e = __expf(-2.0f * a);
        float h = copysignf((1.0f - e) / (1.0f + e), v);

        h_out[((long long)t * NB + b) * NH + j] = h;  // coalesced 512 B per chain
        hsh[cid][hb ^ 1][j] = h;
        __syncthreads();
        hb ^= 1;
    }

    // logits = h_last @ Why + by (per chain)
    if (j < NO) {
        float acc = by[j];
#pragma unroll 8
        for (int k = 0; k < NH; k++)
            acc = fmaf(hsh[cid][hb][k], Why[k * NO + j], acc);
        out[b * NO + j] = acc;
    }
}

extern "C" void kernel_launch(void* const* d_in, const int* in_sizes, int n_in,
                              void* d_out, int out_size) {
    const float* x   = (const float*)d_in[0];
    const float* Wxh = (const float*)d_in[1];
    const float* Whh = (const float*)d_in[2];
    const float* Why = (const float*)d_in[3];
    const float* bh  = (const float*)d_in[4];
    const float* by  = (const float*)d_in[5];
    float* out = (float*)d_out;

    int seq = in_sizes[0] / (NB * NI);  // 2048
    if (seq > S_MAX) seq = S_MAX;

    xw_gemm_kernel<<<seq, 512>>>(x, Wxh, bh, seq);
    rnn_scan_kernel<<<NB / 2, 256>>>(Whh, Why, by, out, seq);
}

// round 5
// speedup vs baseline: 1.1252x; 1.1252x over previous
#include <cuda_runtime.h>

#define NH 128
#define NI 64
#define NO 10
#define NB 128
#define S_MAX 2048

// 128 MiB scratch for the precomputed input projection xW[S,B,H].
__device__ __align__(16) float g_xw[(size_t)S_MAX * NB * NH];

// ---- packed f32x2 helpers (sm_100+ PTX) ----
__device__ __forceinline__ unsigned long long ffma2(unsigned long long a,
                                                    unsigned long long b,
                                                    unsigned long long c) {
    unsigned long long d;
    asm("fma.rn.f32x2 %0, %1, %2, %3;" : "=l"(d) : "l"(a), "l"(b), "l"(c));
    return d;
}
__device__ __forceinline__ unsigned long long packf2(float lo, float hi) {
    unsigned long long r;
    asm("mov.b64 %0, {%1, %2};" : "=l"(r) : "f"(lo), "f"(hi));
    return r;
}
__device__ __forceinline__ float2 unpackf2(unsigned long long v) {
    float2 f;
    asm("mov.b64 {%0, %1}, %2;" : "=f"(f.x), "=f"(f.y) : "l"(v));
    return f;
}

// ============================================================
// K1: xW[s,b,j] = x[s,b,:] @ Wxh[:,j] + bh[j]
// grid = (seq, 2): CTA handles 64 batch rows. block = 512.
// ============================================================
__global__ void __launch_bounds__(512, 1) xw_gemm_kernel(
    const float* __restrict__ x, const float* __restrict__ Wxh,
    const float* __restrict__ bh, int seq)
{
    const int s = blockIdx.x;
    const int bbase = blockIdx.y * 64;
    __shared__ __align__(16) float xs[64 * NI];  // 16 KB

    const float4* xin =
        reinterpret_cast<const float4*>(x + ((long long)s * NB + bbase) * NI);
    float4* xs4 = reinterpret_cast<float4*>(xs);
#pragma unroll
    for (int i = threadIdx.x; i < 64 * NI / 4; i += 512) xs4[i] = xin[i];

    const int j = threadIdx.x & 127;
    const int p = threadIdx.x >> 7;  // 0..3

    unsigned long long w2[NI / 2];
#pragma unroll
    for (int m = 0; m < NI / 2; m++)
        w2[m] = packf2(Wxh[(2 * m) * NH + j], Wxh[(2 * m + 1) * NH + j]);
    const unsigned long long bias2 = packf2(bh[j], 0.0f);
    __syncthreads();

#pragma unroll
    for (int b = p; b < 64; b += 4) {
        const ulonglong2* xr = reinterpret_cast<const ulonglong2*>(xs + b * NI);
        unsigned long long a0 = bias2, a1 = 0ull, a2 = 0ull, a3 = 0ull;
#pragma unroll
        for (int m = 0; m < NI / 4; m++) {
            ulonglong2 xv = xr[m];
            if (m & 1) { a2 = ffma2(xv.x, w2[2 * m], a2); a3 = ffma2(xv.y, w2[2 * m + 1], a3); }
            else       { a0 = ffma2(xv.x, w2[2 * m], a0); a1 = ffma2(xv.y, w2[2 * m + 1], a1); }
        }
        float2 f0 = unpackf2(a0), f1 = unpackf2(a1), f2 = unpackf2(a2), f3 = unpackf2(a3);
        g_xw[((long long)s * NB + bbase + b) * NH + j] =
            ((f0.x + f0.y) + (f1.x + f1.y)) + ((f2.x + f2.y) + (f3.x + f3.y));
    }
}

// ============================================================
// K2: sequential scan with K-split partial exchange.
// grid = NB (1 chain per CTA/SM), block = 128.
// Warp w owns columns [32w,32w+32) AND K-slice [32w,32w+32).
// Lane l computes partials for columns 4l..4l+3 over the warp's own
// 32-element K-slice (8 batched broadcast LDS.128 of OWN h slice,
// ordered by syncwarp). Cross-warp exchange via a partial array:
// STS.128 -> barrier -> 4x LDS.32 -> reduce + xw + bias -> tanh.
// ============================================================
__global__ void __launch_bounds__(NH, 1) rnn_scan_kernel(
    const float* __restrict__ Whh, const float* __restrict__ Why,
    const float* __restrict__ bh, const float* __restrict__ by,
    float* __restrict__ out, int seq)
{
    const int b   = blockIdx.x;
    const int tid = threadIdx.x;
    const int w   = tid >> 5;   // warp = K-slice index
    const int l   = tid & 31;

    // Weights: wp[c'][kk] packs Whh[k][4l+c'] for k-pair (32w+2kk, 32w+2kk+1).
    unsigned long long wp[4][16];
#pragma unroll
    for (int c = 0; c < 4; c++) {
        const int col = 4 * l + c;
#pragma unroll
        for (int kk = 0; kk < 16; kk++) {
            const int k = 32 * w + 2 * kk;
            wp[c][kk] = packf2(Whh[k * NH + col], Whh[(k + 1) * NH + col]);
        }
    }
    const float bias = bh[tid];

    __shared__ __align__(16) float hbuf[2][NH];        // parity-swapped h
    __shared__ __align__(16) float part[2][4][NH];     // double-buffered partials
    hbuf[0][tid] = 0.0f;

    // xw prefetch ring (depth 4) for OWN column tid
    const float* xwb = g_xw + (long long)b * NH + tid;
    float xq[4];
#pragma unroll
    for (int q = 0; q < 4; q++)
        xq[q] = (q < seq) ? xwb[(long long)q * NB * NH] : 0.0f;

    float* h_out = out + NB * NO;
    __syncthreads();

#pragma unroll 4
    for (int t = 0; t < seq; t++) {
        const int pb = t & 1;

        // ---- batched load of OWN warp's h slice (8 broadcast LDS.128) ----
        ulonglong2 hv[8];
        const ulonglong2* h2 =
            reinterpret_cast<const ulonglong2*>(&hbuf[pb][32 * w]);
#pragma unroll
        for (int m = 0; m < 8; m++) hv[m] = h2[m];

        // ---- 32-term partials for columns 4l..4l+3 (64 FFMA2) ----
        unsigned long long a0 = 0ull, a1 = 0ull, a2 = 0ull, a3 = 0ull;
#pragma unroll
        for (int m = 0; m < 8; m++) {
            a0 = ffma2(hv[m].x, wp[0][2 * m], a0);
            a0 = ffma2(hv[m].y, wp[0][2 * m + 1], a0);
            a1 = ffma2(hv[m].x, wp[1][2 * m], a1);
            a1 = ffma2(hv[m].y, wp[1][2 * m + 1], a1);
            a2 = ffma2(hv[m].x, wp[2][2 * m], a2);
            a2 = ffma2(hv[m].y, wp[2][2 * m + 1], a2);
            a3 = ffma2(hv[m].x, wp[3][2 * m], a3);
            a3 = ffma2(hv[m].y, wp[3][2 * m + 1], a3);
        }
        float2 f0 = unpackf2(a0), f1 = unpackf2(a1),
               f2 = unpackf2(a2), f3 = unpackf2(a3);
        float4 pr = make_float4(f0.x + f0.y, f1.x + f1.y,
                                f2.x + f2.y, f3.x + f3.y);
        *reinterpret_cast<float4*>(&part[pb][w][4 * l]) = pr;  // conflict-free

        // xw consume + refill (covers DRAM latency across 4 steps)
        const float xwv = xq[t & 3];
        if (t + 4 < seq) xq[t & 3] = xwb[(long long)(t + 4) * NB * NH];

        __syncthreads();

        // ---- reduce 4 partials for OWN column tid ----
        float v = ((part[pb][0][tid] + part[pb][1][tid]) +
                   (part[pb][2][tid] + part[pb][3][tid])) + xwv + bias;

        // accurate tanh (approx-tanh's 1e-3 abs error would random-walk
        // past tolerance over 2048 steps)
        float a = fabsf(v);
        float e = __expf(-2.0f * a);
        float h = copysignf((1.0f - e) / (1.0f + e), v);

        h_out[((long long)t * NB + b) * NH + tid] = h;  // coalesced 512 B
        hbuf[pb ^ 1][tid] = h;   // own-warp slice; next step reads own slice only
        __syncwarp();
    }

    __syncthreads();
    // ---- logits = h_last @ Why + by ----
    if (tid < NO) {
        float acc = by[tid];
#pragma unroll 8
        for (int k = 0; k < NH; k++)
            acc = fmaf(hbuf[seq & 1][k], Why[k * NO + tid], acc);
        out[b * NO + tid] = acc;
    }
}

extern "C" void kernel_launch(void* const* d_in, const int* in_sizes, int n_in,
                              void* d_out, int out_size) {
    const float* x   = (const float*)d_in[0];
    const float* Wxh = (const float*)d_in[1];
    const float* Whh = (const float*)d_in[2];
    const float* Why = (const float*)d_in[3];
    const float* bh  = (const float*)d_in[4];
    const float* by  = (const float*)d_in[5];
    float* out = (float*)d_out;

    int seq = in_sizes[0] / (NB * NI);  // 2048
    if (seq > S_MAX) seq = S_MAX;

    dim3 g1(seq, 2);
    xw_gemm_kernel<<<g1, 512>>>(x, Wxh, bh, seq);
    rnn_scan_kernel<<<NB, NH>>>(Whh, Why, bh, by, out, seq);
}

// round 6
// speedup vs baseline: 1.5883x; 1.4116x over previous
#include <cuda_runtime.h>

#define NH 128
#define NI 64
#define NO 10
#define NB 128
#define S_MAX 2048

// 128 MiB scratch for the precomputed input projection xW[S,B,H].
__device__ __align__(16) float g_xw[(size_t)S_MAX * NB * NH];

// ---- packed f32x2 helpers (sm_100+ PTX) ----
__device__ __forceinline__ unsigned long long ffma2(unsigned long long a,
                                                    unsigned long long b,
                                                    unsigned long long c) {
    unsigned long long d;
    asm("fma.rn.f32x2 %0, %1, %2, %3;" : "=l"(d) : "l"(a), "l"(b), "l"(c));
    return d;
}
__device__ __forceinline__ unsigned long long packf2(float lo, float hi) {
    unsigned long long r;
    asm("mov.b64 %0, {%1, %2};" : "=l"(r) : "f"(lo), "f"(hi));
    return r;
}
__device__ __forceinline__ float2 unpackf2(unsigned long long v) {
    float2 f;
    asm("mov.b64 {%0, %1}, %2;" : "=f"(f.x), "=f"(f.y) : "l"(v));
    return f;
}

// ============================================================
// K1: xW[s,b,j] = x[s,b,:] @ Wxh[:,j] + bh[j]
// grid = (seq, 4): CTA handles 32 batch rows. block = 256.
// ============================================================
__global__ void __launch_bounds__(256, 1) xw_gemm_kernel(
    const float* __restrict__ x, const float* __restrict__ Wxh,
    const float* __restrict__ bh, int seq)
{
    const int s = blockIdx.x;
    const int bbase = blockIdx.y * 32;
    __shared__ __align__(16) float xs[32 * NI];  // 8 KB

    const float4* xin =
        reinterpret_cast<const float4*>(x + ((long long)s * NB + bbase) * NI);
    float4* xs4 = reinterpret_cast<float4*>(xs);
#pragma unroll
    for (int i = threadIdx.x; i < 32 * NI / 4; i += 256) xs4[i] = xin[i];

    const int j = threadIdx.x & 127;
    const int p = threadIdx.x >> 7;  // 0..1

    unsigned long long w2[NI / 2];
#pragma unroll
    for (int m = 0; m < NI / 2; m++)
        w2[m] = packf2(Wxh[(2 * m) * NH + j], Wxh[(2 * m + 1) * NH + j]);
    const unsigned long long bias2 = packf2(bh[j], 0.0f);
    __syncthreads();

#pragma unroll
    for (int b = p; b < 32; b += 2) {
        const ulonglong2* xr = reinterpret_cast<const ulonglong2*>(xs + b * NI);
        unsigned long long a0 = bias2, a1 = 0ull, a2 = 0ull, a3 = 0ull;
#pragma unroll
        for (int m = 0; m < NI / 4; m++) {
            ulonglong2 xv = xr[m];
            if (m & 1) { a2 = ffma2(xv.x, w2[2 * m], a2); a3 = ffma2(xv.y, w2[2 * m + 1], a3); }
            else       { a0 = ffma2(xv.x, w2[2 * m], a0); a1 = ffma2(xv.y, w2[2 * m + 1], a1); }
        }
        float2 f0 = unpackf2(a0), f1 = unpackf2(a1), f2 = unpackf2(a2), f3 = unpackf2(a3);
        g_xw[((long long)s * NB + bbase + b) * NH + j] =
            ((f0.x + f0.y) + (f1.x + f1.y)) + ((f2.x + f2.y) + (f3.x + f3.y));
    }
}

// ============================================================
// K2: sequential scan with K-split partial exchange (R5 structure).
// grid = NB (1 chain per CTA/SM), block = 128.
// Warp w owns columns [32w,32w+32) AND K-slice [32w,32w+32).
// ONLY CHANGE vs R5: tanh division uses __fdividef (MUFU.RCP path,
// ~2 ulp since denominator is in [1,2]) instead of div.rn.f32's
// ~100-cycle software sequence on the recurrence critical path.
// ============================================================
__global__ void __launch_bounds__(NH, 1) rnn_scan_kernel(
    const float* __restrict__ Whh, const float* __restrict__ Why,
    const float* __restrict__ bh, const float* __restrict__ by,
    float* __restrict__ out, int seq)
{
    const int b   = blockIdx.x;
    const int tid = threadIdx.x;
    const int w   = tid >> 5;   // warp = K-slice index
    const int l   = tid & 31;

    // Weights: wp[c'][kk] packs Whh[k][4l+c'] for k-pair (32w+2kk, 32w+2kk+1).
    unsigned long long wp[4][16];
#pragma unroll
    for (int c = 0; c < 4; c++) {
        const int col = 4 * l + c;
#pragma unroll
        for (int kk = 0; kk < 16; kk++) {
            const int k = 32 * w + 2 * kk;
            wp[c][kk] = packf2(Whh[k * NH + col], Whh[(k + 1) * NH + col]);
        }
    }
    const float bias = bh[tid];

    __shared__ __align__(16) float hbuf[2][NH];        // parity-swapped h
    __shared__ __align__(16) float part[2][4][NH];     // double-buffered partials
    hbuf[0][tid] = 0.0f;

    // xw prefetch ring (depth 4) for OWN column tid
    const float* xwb = g_xw + (long long)b * NH + tid;
    float xq[4];
#pragma unroll
    for (int q = 0; q < 4; q++)
        xq[q] = (q < seq) ? xwb[(long long)q * NB * NH] : 0.0f;

    float* h_out = out + NB * NO;
    __syncthreads();

#pragma unroll 4
    for (int t = 0; t < seq; t++) {
        const int pb = t & 1;

        // ---- batched load of OWN warp's h slice (8 broadcast LDS.128) ----
        ulonglong2 hv[8];
        const ulonglong2* h2 =
            reinterpret_cast<const ulonglong2*>(&hbuf[pb][32 * w]);
#pragma unroll
        for (int m = 0; m < 8; m++) hv[m] = h2[m];

        // ---- 32-term partials for columns 4l..4l+3 (64 FFMA2) ----
        unsigned long long a0 = 0ull, a1 = 0ull, a2 = 0ull, a3 = 0ull;
#pragma unroll
        for (int m = 0; m < 8; m++) {
            a0 = ffma2(hv[m].x, wp[0][2 * m], a0);
            a0 = ffma2(hv[m].y, wp[0][2 * m + 1], a0);
            a1 = ffma2(hv[m].x, wp[1][2 * m], a1);
            a1 = ffma2(hv[m].y, wp[1][2 * m + 1], a1);
            a2 = ffma2(hv[m].x, wp[2][2 * m], a2);
            a2 = ffma2(hv[m].y, wp[2][2 * m + 1], a2);
            a3 = ffma2(hv[m].x, wp[3][2 * m], a3);
            a3 = ffma2(hv[m].y, wp[3][2 * m + 1], a3);
        }
        float2 f0 = unpackf2(a0), f1 = unpackf2(a1),
               f2 = unpackf2(a2), f3 = unpackf2(a3);
        float4 pr = make_float4(f0.x + f0.y, f1.x + f1.y,
                                f2.x + f2.y, f3.x + f3.y);
        *reinterpret_cast<float4*>(&part[pb][w][4 * l]) = pr;  // conflict-free

        // xw consume + refill (covers DRAM latency across 4 steps)
        const float xwv = xq[t & 3];
        if (t + 4 < seq) xq[t & 3] = xwb[(long long)(t + 4) * NB * NH];

        __syncthreads();

        // ---- reduce 4 partials for OWN column tid ----
        float v = ((part[pb][0][tid] + part[pb][1][tid]) +
                   (part[pb][2][tid] + part[pb][3][tid])) + xwv + bias;

        // tanh: exp2 + fast reciprocal (denominator in [1,2] -> ~2 ulp).
        float a = fabsf(v);
        float e = __expf(-2.0f * a);
        float r = __fdividef(1.0f - e, 1.0f + e);
        float h = copysignf(r, v);

        h_out[((long long)t * NB + b) * NH + tid] = h;  // coalesced 512 B
        hbuf[pb ^ 1][tid] = h;   // own-warp slice; next step reads own slice only
        __syncwarp();
    }

    __syncthreads();
    // ---- logits = h_last @ Why + by ----
    if (tid < NO) {
        float acc = by[tid];
#pragma unroll 8
        for (int k = 0; k < NH; k++)
            acc = fmaf(hbuf[seq & 1][k], Why[k * NO + tid], acc);
        out[b * NO + tid] = acc;
    }
}

extern "C" void kernel_launch(void* const* d_in, const int* in_sizes, int n_in,
                              void* d_out, int out_size) {
    const float* x   = (const float*)d_in[0];
    const float* Wxh = (const float*)d_in[1];
    const float* Whh = (const float*)d_in[2];
    const float* Why = (const float*)d_in[3];
    const float* bh  = (const float*)d_in[4];
    const float* by  = (const float*)d_in[5];
    float* out = (float*)d_out;

    int seq = in_sizes[0] / (NB * NI);  // 2048
    if (seq > S_MAX) seq = S_MAX;

    dim3 g1(seq, 4);
    xw_gemm_kernel<<<g1, 256>>>(x, Wxh, bh, seq);
    rnn_scan_kernel<<<NB, NH>>>(Whh, Why, bh, by, out, seq);
}

// round 7
// speedup vs baseline: 1.6073x; 1.0120x over previous
#include <cuda_runtime.h>

#define NH 128
#define NI 64
#define NO 10
#define NB 128
#define S_MAX 2048

// 128 MiB scratch for the precomputed input projection xW[S,B,H].
__device__ __align__(16) float g_xw[(size_t)S_MAX * NB * NH];

// ---- packed f32x2 helpers (sm_100+ PTX) ----
__device__ __forceinline__ unsigned long long ffma2(unsigned long long a,
                                                    unsigned long long b,
                                                    unsigned long long c) {
    unsigned long long d;
    asm("fma.rn.f32x2 %0, %1, %2, %3;" : "=l"(d) : "l"(a), "l"(b), "l"(c));
    return d;
}
__device__ __forceinline__ unsigned long long addf2(unsigned long long a,
                                                    unsigned long long b) {
    unsigned long long d;
    asm("add.rn.f32x2 %0, %1, %2;" : "=l"(d) : "l"(a), "l"(b));
    return d;
}
__device__ __forceinline__ unsigned long long packf2(float lo, float hi) {
    unsigned long long r;
    asm("mov.b64 %0, {%1, %2};" : "=l"(r) : "f"(lo), "f"(hi));
    return r;
}
__device__ __forceinline__ float2 unpackf2(unsigned long long v) {
    float2 f;
    asm("mov.b64 {%0, %1}, %2;" : "=f"(f.x), "=f"(f.y) : "l"(v));
    return f;
}

// tanh(v) = 2/(1+exp(-2v)) - 1, branchless MUFU path.
// mul -> EX2 -> add -> RCP -> FMA.  v->+inf: ex2->0, rcp(1)=1, h=+1.
// v->-inf: ex2->inf, rcp(inf)=0, h=-1.  Abs error ~1e-7 midrange.
__device__ __forceinline__ float tanh_fast(float v) {
    float t = v * -2.8853900817779268f;  // -2*log2(e)
    float e, r;
    asm("ex2.approx.f32 %0, %1;" : "=f"(e) : "f"(t));
    asm("rcp.approx.f32 %0, %1;" : "=f"(r) : "f"(e + 1.0f));
    return fmaf(2.0f, r, -1.0f);
}

// ============================================================
// K1: xW[s,b,j] = x[s,b,:] @ Wxh[:,j] + bh[j]
// grid = (seq, 8): CTA handles 16 batch rows. block = 128.
// ============================================================
__global__ void __launch_bounds__(128, 1) xw_gemm_kernel(
    const float* __restrict__ x, const float* __restrict__ Wxh,
    const float* __restrict__ bh, int seq)
{
    const int s = blockIdx.x;
    const int bbase = blockIdx.y * 16;
    __shared__ __align__(16) float xs[16 * NI];  // 4 KB

    const float4* xin =
        reinterpret_cast<const float4*>(x + ((long long)s * NB + bbase) * NI);
    float4* xs4 = reinterpret_cast<float4*>(xs);
#pragma unroll
    for (int i = threadIdx.x; i < 16 * NI / 4; i += 128) xs4[i] = xin[i];

    const int j = threadIdx.x;

    unsigned long long w2[NI / 2];
#pragma unroll
    for (int m = 0; m < NI / 2; m++)
        w2[m] = packf2(Wxh[(2 * m) * NH + j], Wxh[(2 * m + 1) * NH + j]);
    const unsigned long long bias2 = packf2(bh[j], 0.0f);
    __syncthreads();

#pragma unroll
    for (int b = 0; b < 16; b++) {
        const ulonglong2* xr = reinterpret_cast<const ulonglong2*>(xs + b * NI);
        unsigned long long a0 = bias2, a1 = 0ull, a2 = 0ull, a3 = 0ull;
#pragma unroll
        for (int m = 0; m < NI / 4; m++) {
            ulonglong2 xv = xr[m];
            if (m & 1) { a2 = ffma2(xv.x, w2[2 * m], a2); a3 = ffma2(xv.y, w2[2 * m + 1], a3); }
            else       { a0 = ffma2(xv.x, w2[2 * m], a0); a1 = ffma2(xv.y, w2[2 * m + 1], a1); }
        }
        float2 f = unpackf2(addf2(addf2(a0, a1), addf2(a2, a3)));
        g_xw[((long long)s * NB + bbase + b) * NH + j] = f.x + f.y;
    }
}

// ============================================================
// K2: sequential scan, K-split partial exchange (R5/R6 structure).
// Changes vs R6: (1) 2 accumulator chains per column -> FFMA2 depth 8,
// merged with packed add; (2) sigmoid-form branchless tanh (one mul,
// EX2, add, RCP, FMA); (3) unroll 2 so the body fits I$ L0.
// ============================================================
__global__ void __launch_bounds__(NH, 1) rnn_scan_kernel(
    const float* __restrict__ Whh, const float* __restrict__ Why,
    const float* __restrict__ bh, const float* __restrict__ by,
    float* __restrict__ out, int seq)
{
    const int b   = blockIdx.x;
    const int tid = threadIdx.x;
    const int w   = tid >> 5;   // warp = K-slice index
    const int l   = tid & 31;

    // wp[c][kk] packs Whh[k][4l+c] for k-pair (32w+2kk, 32w+2kk+1).
    unsigned long long wp[4][16];
#pragma unroll
    for (int c = 0; c < 4; c++) {
        const int col = 4 * l + c;
#pragma unroll
        for (int kk = 0; kk < 16; kk++) {
            const int k = 32 * w + 2 * kk;
            wp[c][kk] = packf2(Whh[k * NH + col], Whh[(k + 1) * NH + col]);
        }
    }
    const float bias = bh[tid];

    __shared__ __align__(16) float hbuf[2][NH];        // parity-swapped h
    __shared__ __align__(16) float part[2][4][NH];     // double-buffered partials
    hbuf[0][tid] = 0.0f;

    // xw prefetch ring (depth 4) for OWN column tid
    const float* xwb = g_xw + (long long)b * NH + tid;
    float xq[4];
#pragma unroll
    for (int q = 0; q < 4; q++)
        xq[q] = (q < seq) ? xwb[(long long)q * NB * NH] : 0.0f;

    float* h_out = out + NB * NO;
    __syncthreads();

#pragma unroll 2
    for (int t = 0; t < seq; t++) {
        const int pb = t & 1;

        // ---- batched load of OWN warp's h slice (8 broadcast LDS.128) ----
        ulonglong2 hv[8];
        const ulonglong2* h2 =
            reinterpret_cast<const ulonglong2*>(&hbuf[pb][32 * w]);
#pragma unroll
        for (int m = 0; m < 8; m++) hv[m] = h2[m];

        // ---- 32-term partials, 2 chains per column (depth 8) ----
        unsigned long long a[4][2];
#pragma unroll
        for (int c = 0; c < 4; c++) { a[c][0] = 0ull; a[c][1] = 0ull; }
#pragma unroll
        for (int m = 0; m < 8; m++) {
#pragma unroll
            for (int c = 0; c < 4; c++) {
                a[c][0] = ffma2(hv[m].x, wp[c][2 * m], a[c][0]);
                a[c][1] = ffma2(hv[m].y, wp[c][2 * m + 1], a[c][1]);
            }
        }
        float4 pr;
        {
            float2 f0 = unpackf2(addf2(a[0][0], a[0][1]));
            float2 f1 = unpackf2(addf2(a[1][0], a[1][1]));
            float2 f2 = unpackf2(addf2(a[2][0], a[2][1]));
            float2 f3 = unpackf2(addf2(a[3][0], a[3][1]));
            pr = make_float4(f0.x + f0.y, f1.x + f1.y, f2.x + f2.y, f3.x + f3.y);
        }
        *reinterpret_cast<float4*>(&part[pb][w][4 * l]) = pr;  // conflict-free

        // xw consume + refill (covers DRAM latency across 4 steps)
        const float xwv = xq[t & 3];
        if (t + 4 < seq) xq[t & 3] = xwb[(long long)(t + 4) * NB * NH];

        __syncthreads();

        // ---- reduce 4 partials for OWN column tid ----
        float v = ((part[pb][0][tid] + part[pb][1][tid]) +
                   (part[pb][2][tid] + part[pb][3][tid])) + xwv + bias;

        float h = tanh_fast(v);

        h_out[((long long)t * NB + b) * NH + tid] = h;  // coalesced 512 B
        hbuf[pb ^ 1][tid] = h;   // own-warp slice; next step reads own slice only
        __syncwarp();
    }

    __syncthreads();
    // ---- logits = h_last @ Why + by ----
    if (tid < NO) {
        float acc = by[tid];
#pragma unroll 8
        for (int k = 0; k < NH; k++)
            acc = fmaf(hbuf[seq & 1][k], Why[k * NO + tid], acc);
        out[b * NO + tid] = acc;
    }
}

extern "C" void kernel_launch(void* const* d_in, const int* in_sizes, int n_in,
                              void* d_out, int out_size) {
    const float* x   = (const float*)d_in[0];
    const float* Wxh = (const float*)d_in[1];
    const float* Whh = (const float*)d_in[2];
    const float* Why = (const float*)d_in[3];
    const float* bh  = (const float*)d_in[4];
    const float* by  = (const float*)d_in[5];
    float* out = (float*)d_out;

    int seq = in_sizes[0] / (NB * NI);  // 2048
    if (seq > S_MAX) seq = S_MAX;

    dim3 g1(seq, 8);
    xw_gemm_kernel<<<g1, 128>>>(x, Wxh, bh, seq);
    rnn_scan_kernel<<<NB, NH>>>(Whh, Why, bh, by, out, seq);
}